// round 4
// baseline (speedup 1.0000x reference)
#include <cuda_runtime.h>
#include <cstdint>
#include <cmath>

#define CB 8192
#define NNODES 25
// group sizes: 25, 9, 7, 6, 6

__constant__ int GIDX[5][25] = {
  {0,1,2,3,4,5,6,7,8,9,10,11,12,13,14,15,16,17,18,19,20,21,22,23,24},
  {0,1,2,3,4,5,6,7,8, 0,0,0,0,0,0,0,0,0,0,0,0,0,0,0,0},
  {0,9,10,11,12,13,14, 0,0,0,0,0,0,0,0,0,0,0,0,0,0,0,0,0,0},
  {6,7,8,12,13,14, 0,0,0,0,0,0,0,0,0,0,0,0,0,0,0,0,0,0,0},
  {3,4,5,9,10,11, 0,0,0,0,0,0,0,0,0,0,0,0,0,0,0,0,0,0,0}
};

// device scratch (no allocations allowed)
__device__ float g_h[(size_t)CB * 53 * 512];      // layer-1 outputs (tf32-rounded)
__device__ float g_xr[(size_t)CB * NNODES * 256]; // tf32-rounded x
__device__ float g_W1r[5 * 256 * 512];            // tf32-rounded W1 [g][k][n]
__device__ float g_W2r[5 * 512 * 256];            // tf32-rounded W2 [g][k][n]

__host__ __device__ constexpr size_t hpre(int g) {
    return g == 0 ? 0 : g == 1 ? 25 : g == 2 ? 34 : g == 3 ? 41 : 47;
}

__device__ __forceinline__ uint32_t smem_u32(const void* p) {
    uint32_t a;
    asm("{ .reg .u64 t; cvta.to.shared.u64 t, %1; cvt.u32.u64 %0, t; }"
        : "=r"(a) : "l"(p));
    return a;
}
__device__ __forceinline__ float tf32r(float v) {
    uint32_t o;
    asm("cvt.rna.tf32.f32 %0, %1;" : "=r"(o) : "f"(v));
    return __uint_as_float(o);
}
__device__ __forceinline__ void cp16(uint32_t dst, const void* src) {
    asm volatile("cp.async.cg.shared.global [%0], [%1], 16;"
                 :: "r"(dst), "l"(src) : "memory");
}
__device__ __forceinline__ void cp_commit() {
    asm volatile("cp.async.commit_group;" ::: "memory");
}
__device__ __forceinline__ void cp_wait2() {
    asm volatile("cp.async.wait_group 2;" ::: "memory");
}
__device__ __forceinline__ void mma_tf32(float* d, const uint32_t* a, const uint32_t* b) {
    asm volatile(
        "mma.sync.aligned.m16n8k8.row.col.f32.tf32.tf32.f32 "
        "{%0,%1,%2,%3}, {%4,%5,%6,%7}, {%8,%9}, {%0,%1,%2,%3};"
        : "+f"(d[0]), "+f"(d[1]), "+f"(d[2]), "+f"(d[3])
        : "r"(a[0]), "r"(a[1]), "r"(a[2]), "r"(a[3]), "r"(b[0]), "r"(b[1]));
}

// ---------------------------------------------------------------------------
// Pre-pass: tf32-round x, W1, W2 into scratch.
// ---------------------------------------------------------------------------
__global__ void round_pre(const float* __restrict__ x,
                          const float* __restrict__ W1,
                          const float* __restrict__ W2) {
    const int t = blockIdx.x * 256 + threadIdx.x;
    constexpr int XN4 = CB * NNODES * 256 / 4;
    constexpr int WN4 = 5 * 256 * 512 / 4;
    if (t < XN4) {
        float4 v = ((const float4*)x)[t];
        v.x = tf32r(v.x); v.y = tf32r(v.y); v.z = tf32r(v.z); v.w = tf32r(v.w);
        ((float4*)g_xr)[t] = v;
    }
    if (t < WN4) {
        float4 v = ((const float4*)W1)[t];
        v.x = tf32r(v.x); v.y = tf32r(v.y); v.z = tf32r(v.z); v.w = tf32r(v.w);
        ((float4*)g_W1r)[t] = v;
        v = ((const float4*)W2)[t];
        v.x = tf32r(v.x); v.y = tf32r(v.y); v.z = tf32r(v.z); v.w = tf32r(v.w);
        ((float4*)g_W2r)[t] = v;
    }
}

// ---------------------------------------------------------------------------
// Fused GCN layer, tf32 mma.sync core, 4-stage cp.async pipeline.
// CTA: 128 rows (BB whole batches) x 128 cols; K in 16-chunks.
// 8 warps as 2(M) x 4(N); per warp 64x32 via m16n8k8 tiles.
// ---------------------------------------------------------------------------
template<int G, int GN, int BB, bool L2>
__global__ __launch_bounds__(256, 2)
void gcn_mma(const float* __restrict__ adj,
             const float* __restrict__ b1,
             const float* __restrict__ b2,
             const float* __restrict__ fw,
             float* __restrict__ dout)
{
    constexpr int K     = L2 ? 512 : 256;
    constexpr int NW    = L2 ? 256 : 512;
    constexpr int KC    = 16;
    constexpr int NC    = K / KC;            // 16 or 32
    constexpr int MROWS = BB * GN;
    constexpr int SA_B  = 128 * 20 * 4;      // 10240 (stride 20 floats, 16B pad)
    constexpr int SB_B  = 16 * 136 * 4;      // 8704
    constexpr int STAGE = SA_B + SB_B;       // 18944
    constexpr int NAOFF = 4 * STAGE;         // 75776 bytes

    extern __shared__ char smem[];
    float* smf = (float*)smem;
    const uint32_t sb = smem_u32(smem);

    const int tid  = threadIdx.x;
    const int lane = tid & 31;
    const int wid  = tid >> 5;
    const int warpM = wid >> 2;   // 0..1
    const int warpN = wid & 3;    // 0..3
    const int batch0 = blockIdx.x * BB;
    const int n0     = blockIdx.y * 128;

    float* hreg = g_h + hpre(G) * (size_t)CB * 512;
    const float* Asrc = L2 ? hreg : g_xr;
    const float* Bsrc = L2 ? (g_W2r + (size_t)G * 512 * 256)
                           : (g_W1r + (size_t)G * 256 * 512);
    const float* bias = L2 ? (b2 + G * 256) : (b1 + G * 512);

    // ---- per-thread staging bases (2 A rows + 2 B rows per thread) ----
    const float* aSrc[2];
    uint32_t aDst[2];
    const float* bSrc[2];
    uint32_t bDst[2];
#pragma unroll
    for (int i = 0; i < 2; ++i) {
        const int idx = i * 256 + tid;       // 0..511
        const int row = idx >> 2, kq = idx & 3;
        const int bq = row / GN;
        const int batch = batch0 + bq;
        const bool valid = (row < MROWS) && (batch < CB);
        const float* s;
        if (L2) s = Asrc + (size_t)(batch0 * GN + row) * 512;
        else    s = Asrc + ((size_t)batch * NNODES + GIDX[G][row - bq * GN]) * 256;
        if (!valid) s = Asrc;
        aSrc[i] = s + kq * 4;
        aDst[i] = row * 80 + kq * 16;
        const int kk = idx >> 5, nq = idx & 31;
        bSrc[i] = Bsrc + (size_t)kk * NW + n0 + nq * 4;
        bDst[i] = SA_B + kk * 544 + nq * 16;
    }

    auto stage = [&](int c, int p) {
        const uint32_t base = sb + p * STAGE;
#pragma unroll
        for (int i = 0; i < 2; ++i)
            cp16(base + aDst[i], aSrc[i] + c * KC);
#pragma unroll
        for (int i = 0; i < 2; ++i)
            cp16(base + bDst[i], bSrc[i] + (size_t)c * KC * NW);
    };

    float acc[4][4][4];
#pragma unroll
    for (int mt = 0; mt < 4; ++mt)
#pragma unroll
        for (int nt = 0; nt < 4; ++nt)
#pragma unroll
            for (int r = 0; r < 4; ++r) acc[mt][nt][r] = 0.f;

    stage(0, 0); cp_commit();
    stage(1, 1); cp_commit();
    stage(2, 2); cp_commit();

    // ---- NA precompute (overlaps the prologue loads) ----
    float* NAs  = smf + NAOFF / 4;
    float* dinv = NAs + BB * GN * GN;
    float* nws  = dinv + BB * GN;
    for (int r = tid; r < BB * GN; r += 256) {
        const int b = r / GN, i = r % GN;
        const int batch = batch0 + b;
        float dv = 0.f;
        if (batch < CB) {
            const float* arow = adj + ((size_t)batch * NNODES + GIDX[G][i]) * NNODES;
            float deg = 1.f;
#pragma unroll
            for (int j = 0; j < GN; ++j) deg += arow[GIDX[G][j]];
            dv = rsqrtf(deg);
        }
        dinv[r] = dv;
    }
    if (L2 && tid == 0) {
        float w[5];
#pragma unroll
        for (int q = 0; q < 5; ++q) w[q] = fw[q];
        float m = w[0];
#pragma unroll
        for (int q = 1; q < 5; ++q) m = fmaxf(m, w[q]);
        float e[5], s = 0.f;
#pragma unroll
        for (int q = 0; q < 5; ++q) { e[q] = expf(w[q] - m); s += e[q]; }
        nws[0] = e[G] / s;
    }
    __syncthreads();
    for (int e = tid; e < BB * GN * GN; e += 256) {
        const int b  = e / (GN * GN);
        const int ij = e - b * GN * GN;
        const int i  = ij / GN, j = ij - i * GN;
        const int batch = batch0 + b;
        float v = 0.f;
        if (batch < CB) {
            v = adj[((size_t)batch * NNODES + GIDX[G][i]) * NNODES + GIDX[G][j]];
            if (i == j) v += 1.f;
            v *= dinv[b * GN + i] * dinv[b * GN + j];
        }
        NAs[e] = v;
    }

    // ---- main K loop: 1 sync per chunk, loads land 3 chunks early ----
    const int aRow = warpM * 64 + (lane >> 2);
    const int aCol = lane & 3;
    const int bRow = lane & 3;
    const int bCol = warpN * 32 + (lane >> 2);

    for (int c = 0; c < NC; ++c) {
        const int p = c & 3;
        cp_wait2();
        __syncthreads();

        const uint32_t* sA = (const uint32_t*)(smem + p * STAGE);
        const uint32_t* sB = (const uint32_t*)(smem + p * STAGE + SA_B);
#pragma unroll
        for (int kc = 0; kc < 2; ++kc) {
            uint32_t a[4][4], b[4][2];
#pragma unroll
            for (int mt = 0; mt < 4; ++mt)
#pragma unroll
                for (int r = 0; r < 4; ++r)
                    a[mt][r] = sA[(aRow + mt * 16 + (r & 1) * 8) * 20 +
                                  kc * 8 + aCol + (r >> 1) * 4];
#pragma unroll
            for (int nt = 0; nt < 4; ++nt)
#pragma unroll
                for (int r = 0; r < 2; ++r)
                    b[nt][r] = sB[(bRow + kc * 8 + r * 4) * 136 + bCol + nt * 8];
#pragma unroll
            for (int mt = 0; mt < 4; ++mt)
#pragma unroll
                for (int nt = 0; nt < 4; ++nt)
                    mma_tf32(acc[mt][nt], a[mt], b[nt]);
        }
        if (c + 3 < NC) stage(c + 3, (c + 3) & 3);
        cp_commit();
    }
    __syncthreads();

    // ---- spill accumulators to S[128][132] (aliases staging buffers) ----
    float* S = smf;
#pragma unroll
    for (int mt = 0; mt < 4; ++mt) {
        const int row0 = warpM * 64 + mt * 16 + (lane >> 2);
#pragma unroll
        for (int nt = 0; nt < 4; ++nt) {
            const int col = warpN * 32 + nt * 8 + (lane & 3) * 2;
            *(float2*)&S[row0 * 132 + col]       = make_float2(acc[mt][nt][0], acc[mt][nt][1]);
            *(float2*)&S[(row0 + 8) * 132 + col] = make_float2(acc[mt][nt][2], acc[mt][nt][3]);
        }
    }
    __syncthreads();

    const float nw = L2 ? nws[0] : 1.f;

    // ---- NA aggregation + bias + ReLU + store ----
    constexpr int NU = MROWS * 16;
    for (int u = tid; u < NU; u += 256) {
        const int r  = u >> 4;
        const int cg = (u & 15) * 8;
        const int b  = r / GN, i = r - b * GN;
        const int batch = batch0 + b;
        if (batch >= CB) continue;

        float o[8];
#pragma unroll
        for (int q = 0; q < 8; ++q) o[q] = 0.f;
        const float* nrow = &NAs[(b * GN + i) * GN];
        const float* sp   = &S[(b * GN) * 132 + cg];
#pragma unroll
        for (int j = 0; j < GN; ++j) {
            const float na = nrow[j];
            const float4 s0 = *(const float4*)&sp[j * 132];
            const float4 s1 = *(const float4*)&sp[j * 132 + 4];
            o[0] += na * s0.x; o[1] += na * s0.y;
            o[2] += na * s0.z; o[3] += na * s0.w;
            o[4] += na * s1.x; o[5] += na * s1.y;
            o[6] += na * s1.z; o[7] += na * s1.w;
        }
        const float4 bv0 = *(const float4*)&bias[n0 + cg];
        const float4 bv1 = *(const float4*)&bias[n0 + cg + 4];
        o[0] += bv0.x; o[1] += bv0.y; o[2] += bv0.z; o[3] += bv0.w;
        o[4] += bv1.x; o[5] += bv1.y; o[6] += bv1.z; o[7] += bv1.w;
#pragma unroll
        for (int q = 0; q < 8; ++q) o[q] = fmaxf(o[q], 0.f);

        if (!L2) {
#pragma unroll
            for (int q = 0; q < 8; ++q) o[q] = tf32r(o[q]);
            float* dst = hreg + (size_t)(batch * GN + i) * 512 + n0 + cg;
            *(float4*)dst       = make_float4(o[0], o[1], o[2], o[3]);
            *(float4*)(dst + 4) = make_float4(o[4], o[5], o[6], o[7]);
        } else {
            float* dst = dout + ((size_t)batch * NNODES + GIDX[G][i]) * 256 + n0 + cg;
            if (G == 0) {
                *(float4*)dst       = make_float4(o[0]*nw, o[1]*nw, o[2]*nw, o[3]*nw);
                *(float4*)(dst + 4) = make_float4(o[4]*nw, o[5]*nw, o[6]*nw, o[7]*nw);
            } else {
                float4 p0 = *(const float4*)dst;
                float4 p1 = *(const float4*)(dst + 4);
                p0.x += o[0]*nw; p0.y += o[1]*nw; p0.z += o[2]*nw; p0.w += o[3]*nw;
                p1.x += o[4]*nw; p1.y += o[5]*nw; p1.z += o[6]*nw; p1.w += o[7]*nw;
                *(float4*)dst       = p0;
                *(float4*)(dst + 4) = p1;
            }
        }
    }
}

static inline int smem_total(int GN, int BB) {
    const int NAOFF = 4 * (128 * 20 * 4 + 16 * 136 * 4);
    int b = NAOFF + (BB * GN * GN + BB * GN + 4) * 4;
    return (b + 15) & ~15;
}

extern "C" void kernel_launch(void* const* d_in, const int* in_sizes, int n_in,
                              void* d_out, int out_size) {
    (void)in_sizes; (void)n_in; (void)out_size;
    const float* x   = (const float*)d_in[0];
    const float* adj = (const float*)d_in[1];
    const float* W1  = (const float*)d_in[2];
    const float* b1  = (const float*)d_in[3];
    const float* W2  = (const float*)d_in[4];
    const float* b2  = (const float*)d_in[5];
    const float* fw  = (const float*)d_in[6];
    float* out = (float*)d_out;

    round_pre<<<51200, 256>>>(x, W1, W2);

#define RUN(G, GN, BB, L2, NY)                                                  \
    do {                                                                        \
        auto kfn = gcn_mma<G, GN, BB, L2>;                                      \
        const int smb = smem_total(GN, BB);                                     \
        cudaFuncSetAttribute(kfn, cudaFuncAttributeMaxDynamicSharedMemorySize,  \
                             smb);                                              \
        dim3 grid((CB + BB - 1) / BB, NY);                                      \
        kfn<<<grid, 256, smb>>>(adj, b1, b2, fw, out);                          \
    } while (0)

    // layer 1 (N=512 -> 4 n-tiles)
    RUN(0, 25,  5, false, 4);
    RUN(1,  9, 14, false, 4);
    RUN(2,  7, 18, false, 4);
    RUN(3,  6, 21, false, 4);
    RUN(4,  6, 21, false, 4);
    // layer 2 (N=256 -> 2 n-tiles); group 0 '=', groups 1-4 ordered '+='
    RUN(0, 25,  5, true, 2);
    RUN(1,  9, 14, true, 2);
    RUN(2,  7, 18, true, 2);
    RUN(3,  6, 21, true, 2);
    RUN(4,  6, 21, true, 2);
#undef RUN
}

// round 5
// speedup vs baseline: 1.3828x; 1.3828x over previous
#include <cuda_runtime.h>
#include <cstdint>
#include <cmath>

#define CB 8192
#define NNODES 25
// group sizes: 25, 9, 7, 6, 6

__constant__ int GIDX[5][25] = {
  {0,1,2,3,4,5,6,7,8,9,10,11,12,13,14,15,16,17,18,19,20,21,22,23,24},
  {0,1,2,3,4,5,6,7,8, 0,0,0,0,0,0,0,0,0,0,0,0,0,0,0,0},
  {0,9,10,11,12,13,14, 0,0,0,0,0,0,0,0,0,0,0,0,0,0,0,0,0,0},
  {6,7,8,12,13,14, 0,0,0,0,0,0,0,0,0,0,0,0,0,0,0,0,0,0,0},
  {3,4,5,9,10,11, 0,0,0,0,0,0,0,0,0,0,0,0,0,0,0,0,0,0,0}
};

// device scratch (no allocations allowed)
__device__ float g_h  [(size_t)CB * 53 * 512];  // ha = NA@h (tf32-rounded)
__device__ float g_xa [(size_t)CB * 53 * 256];  // xa = NA@x (tf32-rounded)
__device__ float g_nat[(size_t)CB * 1096];      // NA, padded, j-major per group
__device__ float g_W1r[5 * 256 * 512];
__device__ float g_W2r[5 * 512 * 256];

__host__ __device__ constexpr size_t hpre(int g) {
    return g == 0 ? 0 : g == 1 ? 25 : g == 2 ? 34 : g == 3 ? 41 : 47;
}
__host__ __device__ constexpr int natoff(int g) {
    // prefix of GN*GNP: 25*32, 9*16, 7*8, 6*8, 6*8
    return g == 0 ? 0 : g == 1 ? 800 : g == 2 ? 944 : g == 3 ? 1000 : 1048;
}

__device__ __forceinline__ uint32_t smem_u32(const void* p) {
    uint32_t a;
    asm("{ .reg .u64 t; cvta.to.shared.u64 t, %1; cvt.u32.u64 %0, t; }"
        : "=r"(a) : "l"(p));
    return a;
}
__device__ __forceinline__ float tf32r(float v) {
    uint32_t o;
    asm("cvt.rna.tf32.f32 %0, %1;" : "=r"(o) : "f"(v));
    return __uint_as_float(o);
}
__device__ __forceinline__ void cp16(uint32_t dst, const void* src) {
    asm volatile("cp.async.cg.shared.global [%0], [%1], 16;"
                 :: "r"(dst), "l"(src) : "memory");
}
__device__ __forceinline__ void cp_commit() {
    asm volatile("cp.async.commit_group;" ::: "memory");
}
__device__ __forceinline__ void cp_wait2() {
    asm volatile("cp.async.wait_group 2;" ::: "memory");
}
__device__ __forceinline__ void mma_tf32(float* d, const uint32_t* a, const uint32_t* b) {
    asm volatile(
        "mma.sync.aligned.m16n8k8.row.col.f32.tf32.tf32.f32 "
        "{%0,%1,%2,%3}, {%4,%5,%6,%7}, {%8,%9}, {%0,%1,%2,%3};"
        : "+f"(d[0]), "+f"(d[1]), "+f"(d[2]), "+f"(d[3])
        : "r"(a[0]), "r"(a[1]), "r"(a[2]), "r"(a[3]), "r"(b[0]), "r"(b[1]));
}
__device__ __forceinline__ uint64_t packf2(float v) {
    uint64_t d;
    asm("mov.b64 %0, {%1, %1};" : "=l"(d) : "r"(__float_as_uint(v)));
    return d;
}
__device__ __forceinline__ void fmaf2(uint64_t& o, uint64_t a, uint64_t b) {
    asm("fma.rn.f32x2 %0, %1, %2, %0;" : "+l"(o) : "l"(a), "l"(b));
}

// ---------------------------------------------------------------------------
// Weight rounding pre-pass
// ---------------------------------------------------------------------------
__global__ void wround(const float* __restrict__ W1, const float* __restrict__ W2) {
    const int t = blockIdx.x * 256 + threadIdx.x;
    constexpr int WN4 = 5 * 256 * 512 / 4;
    if (t < WN4) {
        float4 v = ((const float4*)W1)[t];
        v.x = tf32r(v.x); v.y = tf32r(v.y); v.z = tf32r(v.z); v.w = tf32r(v.w);
        ((float4*)g_W1r)[t] = v;
        v = ((const float4*)W2)[t];
        v.x = tf32r(v.x); v.y = tf32r(v.y); v.z = tf32r(v.z); v.w = tf32r(v.w);
        ((float4*)g_W2r)[t] = v;
    }
}

// ---------------------------------------------------------------------------
// Pre-pass: per batch, build NA per group (store padded j-major) and
// xa = NA @ x (tf32-rounded).
// ---------------------------------------------------------------------------
template<int G, int GN, int GNP>
__device__ void aggx_group(int b, int tid, const float* xs, const float* adjs,
                           float* na_s, float* dinv) {
    if (tid < GN) {
        float deg = 1.f;
#pragma unroll
        for (int j = 0; j < GN; ++j)
            deg += adjs[GIDX[G][tid] * 25 + GIDX[G][j]];
        dinv[tid] = rsqrtf(deg);
    }
    __syncthreads();
    for (int e = tid; e < GN * GN; e += 256) {
        const int i = e / GN, j = e - i * GN;
        float v = adjs[GIDX[G][i] * 25 + GIDX[G][j]] + (i == j ? 1.f : 0.f);
        na_s[e] = v * dinv[i] * dinv[j];
    }
    __syncthreads();
    float* natd = g_nat + (size_t)b * 1096 + natoff(G);
    for (int e = tid; e < GN * GNP; e += 256) {
        const int j = e / GNP, i = e - j * GNP;
        natd[e] = (i < GN) ? na_s[i * GN + j] : 0.f;
    }
    float* xad = g_xa + hpre(G) * (size_t)CB * 256 + (size_t)b * GN * 256;
    for (int u = tid; u < GN * 64; u += 256) {
        const int i = u >> 6, c = (u & 63) * 4;
        float4 o = make_float4(0.f, 0.f, 0.f, 0.f);
#pragma unroll
        for (int j = 0; j < GN; ++j) {
            const float na = na_s[i * GN + j];
            const float4 xv = *(const float4*)&xs[GIDX[G][j] * 260 + c];
            o.x += na * xv.x; o.y += na * xv.y;
            o.z += na * xv.z; o.w += na * xv.w;
        }
        o.x = tf32r(o.x); o.y = tf32r(o.y); o.z = tf32r(o.z); o.w = tf32r(o.w);
        *(float4*)&xad[i * 256 + c] = o;
    }
    __syncthreads();
}

__global__ __launch_bounds__(256)
void aggx(const float* __restrict__ x, const float* __restrict__ adj) {
    __shared__ float xs[25 * 260];
    __shared__ float adjs[625];
    __shared__ float na_s[625];
    __shared__ float dinv[25];
    const int b = blockIdx.x, tid = threadIdx.x;
    for (int e = tid; e < 25 * 256; e += 256) {
        const int row = e >> 8, col = e & 255;
        xs[row * 260 + col] = x[(size_t)b * 6400 + e];
    }
    for (int e = tid; e < 625; e += 256) adjs[e] = adj[(size_t)b * 625 + e];
    __syncthreads();
    aggx_group<0, 25, 32>(b, tid, xs, adjs, na_s, dinv);
    aggx_group<1,  9, 16>(b, tid, xs, adjs, na_s, dinv);
    aggx_group<2,  7,  8>(b, tid, xs, adjs, na_s, dinv);
    aggx_group<3,  6,  8>(b, tid, xs, adjs, na_s, dinv);
    aggx_group<4,  6,  8>(b, tid, xs, adjs, na_s, dinv);
}

// ---------------------------------------------------------------------------
// Layer 1: h' = NA @ relu(xa @ W1 + b1)   (ha stored tf32-rounded)
// CTA: BB whole batches (<=128 rows) x 128 cols; K=256, 16-chunks, 4 stages.
// ---------------------------------------------------------------------------
template<int G, int GN, int BB, int GNP, int NIB>
__global__ __launch_bounds__(256, 2)
void gcn_l1(const float* __restrict__ b1)
{
    constexpr int K     = 256;
    constexpr int NW    = 512;
    constexpr int KC    = 16;
    constexpr int NC    = K / KC;
    constexpr int MROWS = BB * GN;
    constexpr int SA_B  = 128 * 20 * 4;
    constexpr int SB_B  = 16 * 136 * 4;
    constexpr int STAGE = SA_B + SB_B;
    constexpr int NATOFF = 4 * STAGE;    // NAt tile above staging buffers

    extern __shared__ char smem[];
    float* smf = (float*)smem;
    const uint32_t sb = smem_u32(smem);

    const int tid  = threadIdx.x;
    const int lane = tid & 31;
    const int wid  = tid >> 5;
    const int warpM = wid >> 2;
    const int warpN = wid & 3;
    const int batch0 = blockIdx.x * BB;
    const int n0     = blockIdx.y * 128;

    const float* Asrc = g_xa + hpre(G) * (size_t)CB * 256;
    const float* Bsrc = g_W1r + (size_t)G * 256 * 512;
    const float* bias = b1 + G * 512;
    float* hdst = g_h + hpre(G) * (size_t)CB * 512;

    // staging addressing
    const float* aSrc[2]; uint32_t aDst[2];
    const float* bSrc[2]; uint32_t bDst[2];
#pragma unroll
    for (int i = 0; i < 2; ++i) {
        const int idx = i * 256 + tid;
        const int row = idx >> 2, kq = idx & 3;
        const bool valid = (row < MROWS) && (batch0 + row / GN < CB);
        aSrc[i] = (valid ? Asrc + (size_t)(batch0 * GN + row) * 256 : Asrc) + kq * 4;
        aDst[i] = row * 80 + kq * 16;
        const int kk = idx >> 5, nq = idx & 31;
        bSrc[i] = Bsrc + (size_t)kk * NW + n0 + nq * 4;
        bDst[i] = SA_B + kk * 544 + nq * 16;
    }
    auto stage = [&](int c, int p) {
        const uint32_t base = sb + p * STAGE;
#pragma unroll
        for (int i = 0; i < 2; ++i) cp16(base + aDst[i], aSrc[i] + c * KC);
#pragma unroll
        for (int i = 0; i < 2; ++i) cp16(base + bDst[i], bSrc[i] + (size_t)c * KC * NW);
    };

    float acc[4][4][4];
#pragma unroll
    for (int mt = 0; mt < 4; ++mt)
#pragma unroll
        for (int nt = 0; nt < 4; ++nt)
#pragma unroll
            for (int r = 0; r < 4; ++r) acc[mt][nt][r] = 0.f;

    stage(0, 0); cp_commit();
    stage(1, 1); cp_commit();
    stage(2, 2); cp_commit();

    // NAt tile load (independent region; overlaps prologue)
    float* NAt_s = smf + NATOFF / 4;
    for (int e = tid; e < BB * GN * GNP; e += 256) {
        const int bb = e / (GN * GNP);
        const int r  = e - bb * (GN * GNP);
        NAt_s[e] = (batch0 + bb < CB)
                 ? g_nat[(size_t)(batch0 + bb) * 1096 + natoff(G) + r] : 0.f;
    }
    // bias regs
    float2 bs[4];
#pragma unroll
    for (int nt = 0; nt < 4; ++nt)
        bs[nt] = *(const float2*)&bias[n0 + warpN * 32 + nt * 8 + (lane & 3) * 2];

    const int aRow = warpM * 64 + (lane >> 2);
    const int aCol = lane & 3;
    const int bRow = lane & 3;
    const int bCol = warpN * 32 + (lane >> 2);

    for (int c = 0; c < NC; ++c) {
        const int p = c & 3;
        cp_wait2();
        __syncthreads();
        const uint32_t* sA = (const uint32_t*)(smem + p * STAGE);
        const uint32_t* sBp = (const uint32_t*)(smem + p * STAGE + SA_B);
#pragma unroll
        for (int kc = 0; kc < 2; ++kc) {
            uint32_t a[4][4], b[4][2];
#pragma unroll
            for (int mt = 0; mt < 4; ++mt)
#pragma unroll
                for (int r = 0; r < 4; ++r)
                    a[mt][r] = sA[(aRow + mt * 16 + (r & 1) * 8) * 20 +
                                  kc * 8 + aCol + (r >> 1) * 4];
#pragma unroll
            for (int nt = 0; nt < 4; ++nt)
#pragma unroll
                for (int r = 0; r < 2; ++r)
                    b[nt][r] = sBp[(bRow + kc * 8 + r * 4) * 136 + bCol + nt * 8];
#pragma unroll
            for (int mt = 0; mt < 4; ++mt)
#pragma unroll
                for (int nt = 0; nt < 4; ++nt)
                    mma_tf32(acc[mt][nt], a[mt], b[nt]);
        }
        if (c + 3 < NC) stage(c + 3, (c + 3) & 3);
        cp_commit();
    }
    __syncthreads();

    // ---- epilogue: two 64-col halves. spill relu(acc+b), aggregate NA@h ----
    float* S = smf;   // [128][68], aliases stage 0-1
    for (int hf = 0; hf < 2; ++hf) {
#pragma unroll
        for (int mt = 0; mt < 4; ++mt) {
            const int row0 = warpM * 64 + mt * 16 + (lane >> 2);
#pragma unroll
            for (int ntl = 0; ntl < 2; ++ntl) {
                const int nt = 2 * hf + ntl;
                const int sc = warpN * 16 + ntl * 8 + (lane & 3) * 2;
                *(float2*)&S[row0 * 68 + sc] =
                    make_float2(fmaxf(acc[mt][nt][0] + bs[nt].x, 0.f),
                                fmaxf(acc[mt][nt][1] + bs[nt].y, 0.f));
                *(float2*)&S[(row0 + 8) * 68 + sc] =
                    make_float2(fmaxf(acc[mt][nt][2] + bs[nt].x, 0.f),
                                fmaxf(acc[mt][nt][3] + bs[nt].y, 0.f));
            }
        }
        __syncthreads();

        constexpr int NU2 = BB * NIB * 16;
        for (int u = tid; u < NU2; u += 256) {
            const int cg = u & 15;
            const int t  = u >> 4;
            const int b  = t / NIB;
            const int i0 = (t - b * NIB) * 8;
            const int batch = batch0 + b;
            if (batch >= CB) continue;
            const int icnt = (GN - i0 < 8) ? (GN - i0) : 8;

            uint64_t o[8][2];
#pragma unroll
            for (int ii = 0; ii < 8; ++ii) { o[ii][0] = 0; o[ii][1] = 0; }
            const float* Srow = S + (b * GN) * 68 + cg * 4;
            const float* natb = NAt_s + b * (GN * GNP) + i0;
#pragma unroll
            for (int j = 0; j < GN; ++j) {
                const ulonglong2 s2 = *(const ulonglong2*)(Srow + (size_t)j * 68);
                const float4 nA = *(const float4*)(natb + j * GNP);
                const float4 nB = *(const float4*)(natb + j * GNP + 4);
                const float na[8] = {nA.x, nA.y, nA.z, nA.w, nB.x, nB.y, nB.z, nB.w};
#pragma unroll
                for (int ii = 0; ii < 8; ++ii) {
                    const uint64_t d = packf2(na[ii]);
                    fmaf2(o[ii][0], d, s2.x);
                    fmaf2(o[ii][1], d, s2.y);
                }
            }
            const int col = n0 + (cg >> 2) * 32 + hf * 16 + (cg & 3) * 4;
#pragma unroll
            for (int ii = 0; ii < 8; ++ii) {
                if (ii >= icnt) break;
                float4 v = make_float4(
                    tf32r(__uint_as_float((uint32_t)o[ii][0])),
                    tf32r(__uint_as_float((uint32_t)(o[ii][0] >> 32))),
                    tf32r(__uint_as_float((uint32_t)o[ii][1])),
                    tf32r(__uint_as_float((uint32_t)(o[ii][1] >> 32))));
                *(float4*)&hdst[(size_t)(batch * GN + i0 + ii) * 512 + col] = v;
            }
        }
        __syncthreads();
    }
}

// ---------------------------------------------------------------------------
// Layer 2: out = relu(ha @ W2 + b2) * nw ; G0 '=', others '+='. Flat M-tiles.
// ---------------------------------------------------------------------------
template<int G, int GN>
__global__ __launch_bounds__(256, 2)
void gcn_l2(const float* __restrict__ b2,
            const float* __restrict__ fw,
            float* __restrict__ dout)
{
    constexpr int K     = 512;
    constexpr int NW    = 256;
    constexpr int KC    = 16;
    constexpr int NC    = K / KC;
    constexpr int R     = CB * GN;
    constexpr int SA_B  = 128 * 20 * 4;
    constexpr int SB_B  = 16 * 136 * 4;
    constexpr int STAGE = SA_B + SB_B;

    extern __shared__ char smem[];
    float* smf = (float*)smem;
    const uint32_t sb = smem_u32(smem);

    const int tid  = threadIdx.x;
    const int lane = tid & 31;
    const int wid  = tid >> 5;
    const int warpM = wid >> 2;
    const int warpN = wid & 3;
    const int r0 = blockIdx.x * 128;
    const int n0 = blockIdx.y * 128;

    const float* Asrc = g_h + hpre(G) * (size_t)CB * 512;
    const float* Bsrc = g_W2r + (size_t)G * 512 * 256;
    const float* bias = b2 + G * 256;

    // softmax weight (per-thread, cheap)
    float nw;
    {
        float w[5];
#pragma unroll
        for (int q = 0; q < 5; ++q) w[q] = fw[q];
        float m = w[0];
#pragma unroll
        for (int q = 1; q < 5; ++q) m = fmaxf(m, w[q]);
        float s = 0.f, e[5];
#pragma unroll
        for (int q = 0; q < 5; ++q) { e[q] = expf(w[q] - m); s += e[q]; }
        nw = e[G] / s;
    }

    const float* aSrc[2]; uint32_t aDst[2];
    const float* bSrc[2]; uint32_t bDst[2];
#pragma unroll
    for (int i = 0; i < 2; ++i) {
        const int idx = i * 256 + tid;
        const int row = idx >> 2, kq = idx & 3;
        const bool valid = (r0 + row < R);
        aSrc[i] = (valid ? Asrc + (size_t)(r0 + row) * 512 : Asrc) + kq * 4;
        aDst[i] = row * 80 + kq * 16;
        const int kk = idx >> 5, nq = idx & 31;
        bSrc[i] = Bsrc + (size_t)kk * NW + n0 + nq * 4;
        bDst[i] = SA_B + kk * 544 + nq * 16;
    }
    auto stage = [&](int c, int p) {
        const uint32_t base = sb + p * STAGE;
#pragma unroll
        for (int i = 0; i < 2; ++i) cp16(base + aDst[i], aSrc[i] + c * KC);
#pragma unroll
        for (int i = 0; i < 2; ++i) cp16(base + bDst[i], bSrc[i] + (size_t)c * KC * NW);
    };

    float acc[4][4][4];
#pragma unroll
    for (int mt = 0; mt < 4; ++mt)
#pragma unroll
        for (int nt = 0; nt < 4; ++nt)
#pragma unroll
            for (int r = 0; r < 4; ++r) acc[mt][nt][r] = 0.f;

    stage(0, 0); cp_commit();
    stage(1, 1); cp_commit();
    stage(2, 2); cp_commit();

    float2 bs[4];
#pragma unroll
    for (int nt = 0; nt < 4; ++nt)
        bs[nt] = *(const float2*)&bias[n0 + warpN * 32 + nt * 8 + (lane & 3) * 2];

    const int aRow = warpM * 64 + (lane >> 2);
    const int aCol = lane & 3;
    const int bRow = lane & 3;
    const int bCol = warpN * 32 + (lane >> 2);

    for (int c = 0; c < NC; ++c) {
        const int p = c & 3;
        cp_wait2();
        __syncthreads();
        const uint32_t* sA = (const uint32_t*)(smem + p * STAGE);
        const uint32_t* sBp = (const uint32_t*)(smem + p * STAGE + SA_B);
#pragma unroll
        for (int kc = 0; kc < 2; ++kc) {
            uint32_t a[4][4], b[4][2];
#pragma unroll
            for (int mt = 0; mt < 4; ++mt)
#pragma unroll
                for (int r = 0; r < 4; ++r)
                    a[mt][r] = sA[(aRow + mt * 16 + (r & 1) * 8) * 20 +
                                  kc * 8 + aCol + (r >> 1) * 4];
#pragma unroll
            for (int nt = 0; nt < 4; ++nt)
#pragma unroll
                for (int r = 0; r < 2; ++r)
                    b[nt][r] = sBp[(bRow + kc * 8 + r * 4) * 136 + bCol + nt * 8];
#pragma unroll
            for (int mt = 0; mt < 4; ++mt)
#pragma unroll
                for (int nt = 0; nt < 4; ++nt)
                    mma_tf32(acc[mt][nt], a[mt], b[nt]);
        }
        if (c + 3 < NC) stage(c + 3, (c + 3) & 3);
        cp_commit();
    }
    __syncthreads();

    // ---- epilogue: spill relu(acc+b)*nw, coalesced RMW to dout ----
    float* S = smf;
    for (int hf = 0; hf < 2; ++hf) {
#pragma unroll
        for (int mt = 0; mt < 4; ++mt) {
            const int row0 = warpM * 64 + mt * 16 + (lane >> 2);
#pragma unroll
            for (int ntl = 0; ntl < 2; ++ntl) {
                const int nt = 2 * hf + ntl;
                const int sc = warpN * 16 + ntl * 8 + (lane & 3) * 2;
                *(float2*)&S[row0 * 68 + sc] =
                    make_float2(fmaxf(acc[mt][nt][0] + bs[nt].x, 0.f) * nw,
                                fmaxf(acc[mt][nt][1] + bs[nt].y, 0.f) * nw);
                *(float2*)&S[(row0 + 8) * 68 + sc] =
                    make_float2(fmaxf(acc[mt][nt][2] + bs[nt].x, 0.f) * nw,
                                fmaxf(acc[mt][nt][3] + bs[nt].y, 0.f) * nw);
            }
        }
        __syncthreads();

        for (int u = tid; u < 128 * 16; u += 256) {
            const int row = u >> 4, cg = u & 15;
            const int gr = r0 + row;
            if (gr >= R) continue;
            const int batch = gr / GN;
            const int node  = gr - batch * GN;
            const int col = n0 + (cg >> 2) * 32 + hf * 16 + (cg & 3) * 4;
            const float4 v = *(const float4*)&S[row * 68 + cg * 4];
            float* dst = dout + ((size_t)batch * NNODES + GIDX[G][node]) * 256 + col;
            if (G == 0) {
                *(float4*)dst = v;
            } else {
                float4 p = *(const float4*)dst;
                p.x += v.x; p.y += v.y; p.z += v.z; p.w += v.w;
                *(float4*)dst = p;
            }
        }
        __syncthreads();
    }
}

extern "C" void kernel_launch(void* const* d_in, const int* in_sizes, int n_in,
                              void* d_out, int out_size) {
    (void)in_sizes; (void)n_in; (void)out_size;
    const float* x   = (const float*)d_in[0];
    const float* adj = (const float*)d_in[1];
    const float* W1  = (const float*)d_in[2];
    const float* b1  = (const float*)d_in[3];
    const float* W2  = (const float*)d_in[4];
    const float* b2  = (const float*)d_in[5];
    const float* fw  = (const float*)d_in[6];
    float* out = (float*)d_out;

    wround<<<640, 256>>>(W1, W2);
    aggx<<<CB, 256>>>(x, adj);

    constexpr int STAGE4 = 4 * (128 * 20 * 4 + 16 * 136 * 4);

#define RUN1(G, GN, BB, GNP, NIB)                                               \
    do {                                                                        \
        auto kfn = gcn_l1<G, GN, BB, GNP, NIB>;                                 \
        const int smb = STAGE4 + BB * GN * GNP * 4;                             \
        cudaFuncSetAttribute(kfn, cudaFuncAttributeMaxDynamicSharedMemorySize,  \
                             smb);                                              \
        dim3 grid((CB + BB - 1) / BB, 4);                                       \
        kfn<<<grid, 256, smb>>>(b1);                                            \
    } while (0)
#define RUN2(G, GN)                                                             \
    do {                                                                        \
        auto kfn = gcn_l2<G, GN>;                                               \
        cudaFuncSetAttribute(kfn, cudaFuncAttributeMaxDynamicSharedMemorySize,  \
                             STAGE4);                                           \
        dim3 grid((CB * GN + 127) / 128, 2);                                    \
        kfn<<<grid, 256, STAGE4>>>(b2, fw, out);                                \
    } while (0)

    RUN1(0, 25,  5, 32, 4);
    RUN1(1,  9, 14, 16, 2);
    RUN1(2,  7, 18,  8, 1);
    RUN1(3,  6, 21,  8, 1);
    RUN1(4,  6, 21,  8, 1);

    RUN2(0, 25);   // '='
    RUN2(1,  9);   // '+=' (stream-ordered, deterministic)
    RUN2(2,  7);
    RUN2(3,  6);
    RUN2(4,  6);
#undef RUN1
#undef RUN2
}